// round 14
// baseline (speedup 1.0000x reference)
#include <cuda_runtime.h>
#include <cuda_fp16.h>
#include <math_constants.h>

#define BB 8
#define CC 512
#define NN 1024
#define HH 8
#define DD 64

// Q/K stored d-major per (b,h):  g_q[((b*HH+h)*DD + d)*NN + n]
__device__ float  g_q[BB*HH*NN*DD];
__device__ float  g_k[BB*HH*NN*DD];
__device__ __half g_s[(size_t)BB*HH*NN*NN];  // 128 MB: unscaled exp'd scores
__device__ float  g_rsinv[BB*HH*NN];         // fp32 1/rowsum per (b,h,q)
__device__ double g_ksc[BB*NN];              // key_scores accumulators (fp64)
__device__ float  g_mp[BB*CC];               // max-pooled (B, C)

// ---- packed f32x2 helpers ---------------------------------------------------
__device__ __forceinline__ unsigned long long f2pack(float lo, float hi) {
    unsigned long long r;
    asm("mov.b64 %0, {%1, %2};" : "=l"(r) : "f"(lo), "f"(hi));
    return r;
}
__device__ __forceinline__ unsigned long long ffma2(unsigned long long a,
                                                    unsigned long long b,
                                                    unsigned long long c) {
    unsigned long long d;
    asm("fma.rn.f32x2 %0, %1, %2, %3;" : "=l"(d) : "l"(a), "l"(b), "l"(c));
    return d;
}
__device__ __forceinline__ float2 f2unpack(unsigned long long v) {
    float lo, hi;
    asm("mov.b64 {%0, %1}, %2;" : "=f"(lo), "=f"(hi) : "l"(v));
    return make_float2(lo, hi);
}
__device__ __forceinline__ float ex2f(float x) {
    float y;
    asm("ex2.approx.ftz.f32 %0, %1;" : "=f"(y) : "f"(x));
    return y;
}
// pack two fp32 into f16x2: lo half = first arg
__device__ __forceinline__ unsigned int h2pack(float lo, float hi) {
    unsigned int d;
    asm("cvt.rn.f16x2.f32 %0, %1, %2;" : "=r"(d) : "f"(hi), "f"(lo));
    return d;
}

// exp(x) for x in [0, 1/32], fp32 degree-4 Taylor (round-6 error budget).
__device__ __forceinline__ float exp_small_f(float x) {
    float p = 1.f / 24.f;
    p = fmaf(p, x, 1.f / 6.f);
    p = fmaf(p, x, 0.5f);
    p = fmaf(p, x, 1.f);
    p = fmaf(p, x, 1.f);
    return p;
}

// ---------------------------------------------------------------------------
// Kernel 1: fused Q/K projection (R9 version, known good).
// ---------------------------------------------------------------------------
__global__ __launch_bounds__(256) void proj_kernel(const float* __restrict__ x,
                                                   const float* __restrict__ W,
                                                   const float* __restrict__ bias) {
    __shared__ float As[16 * 132];
    __shared__ float Bs[16 * 68];
    int tid = threadIdx.x;
    int tx  = tid & 31;
    int wid = tid >> 5;
    int jq  = tx & 15;
    int mg  = wid * 2 + (tx >> 4);
    int j0 = blockIdx.x * 64;
    int m0 = blockIdx.y * 128;
    int b  = m0 >> 10;
    int n0 = m0 & 1023;
    const float* xb = x + (size_t)b * CC * NN;

    unsigned long long acc[4][4];
    #pragma unroll
    for (int i = 0; i < 4; i++)
        #pragma unroll
        for (int j = 0; j < 4; j++) acc[i][j] = 0ull;

    for (int kb = 0; kb < CC; kb += 16) {
        #pragma unroll
        for (int p = 0; p < 8; p++) {
            int e = tid + p * 256;
            int kk = e >> 7, mm = e & 127;
            As[kk * 132 + mm] = xb[(kb + kk) * NN + n0 + mm];
        }
        #pragma unroll
        for (int p = 0; p < 4; p++) {
            int e = tid + p * 256;
            int kk = e & 15, jl = e >> 4;
            Bs[kk * 68 + jl] = W[(size_t)(j0 + jl) * CC + kb + kk];
        }
        __syncthreads();
        #pragma unroll
        for (int kk = 0; kk < 16; kk++) {
            float4 a0 = *(const float4*)&As[kk * 132 + mg * 8];
            float4 a1 = *(const float4*)&As[kk * 132 + mg * 8 + 4];
            float4 bq = *(const float4*)&Bs[kk * 68 + 4 * jq];
            unsigned long long A[4] = { f2pack(a0.x, a0.y), f2pack(a0.z, a0.w),
                                        f2pack(a1.x, a1.y), f2pack(a1.z, a1.w) };
            unsigned long long Bd[4] = { f2pack(bq.x, bq.x), f2pack(bq.y, bq.y),
                                         f2pack(bq.z, bq.z), f2pack(bq.w, bq.w) };
            #pragma unroll
            for (int am = 0; am < 4; am++)
                #pragma unroll
                for (int j = 0; j < 4; j++)
                    acc[am][j] = ffma2(A[am], Bd[j], acc[am][j]);
        }
        __syncthreads();
    }

    #pragma unroll
    for (int j = 0; j < 4; j++) {
        int jg = j0 + 4 * jq + j;
        float bsv = bias[jg];
        int head = (jg & 511) >> 6;
        int dd   = jg & 63;
        float* dst = ((jg < 512) ? g_q : g_k)
                   + ((size_t)(b * HH + head) * DD + dd) * NN + n0 + mg * 8;
        float2 u0 = f2unpack(acc[0][j]);
        float2 u1 = f2unpack(acc[1][j]);
        float2 u2 = f2unpack(acc[2][j]);
        float2 u3 = f2unpack(acc[3][j]);
        *(float4*)&dst[0] = make_float4(u0.x + bsv, u0.y + bsv, u1.x + bsv, u1.y + bsv);
        *(float4*)&dst[4] = make_float4(u2.x + bsv, u2.y + bsv, u3.x + bsv, u3.y + bsv);
    }
}

// ---------------------------------------------------------------------------
// Kernel 2: per-(b,h,32q) exp'd scores -> g_s (fp16, unscaled) + 1/rowsum.
// (R13 version, known good: 3 blocks/SM, 8q x 4k microtile.)
// ---------------------------------------------------------------------------
#define QS_STRIDE 36
#define KS_STRIDE 260
#define SM_QS   0
#define SM_KS   (64*QS_STRIDE)
#define SM_RP   (SM_KS + 64*KS_STRIDE)
#define SMEM2   ((SM_RP + 64) * 4)

__global__ __launch_bounds__(256, 3) void attn_kernel() {
    extern __shared__ float sm[];
    float* Qs    = sm + SM_QS;     // [64 d][36: 32q + pad]
    float* Ks    = sm + SM_KS;     // [64 d][260: 256k + pad]
    float* rpart = sm + SM_RP;     // [2 strips][32 rows]

    const float QSCALE = 0.18033688f;          // log2(e)/8
    int tid = threadIdx.x;
    int b  = blockIdx.x >> 8;
    int h  = (blockIdx.x >> 5) & 7;
    int q0 = (blockIdx.x & 31) << 5;
    int tx = tid & 31, w = tid >> 5;
    int qg = (w & 3) * 8;
    int ks = w >> 2;
    int kbase = ks * 128 + 4 * tx;
    const unsigned long long NEG4 = f2pack(-4.f, -4.f);

    const float* Qg = g_q + (size_t)(b * HH + h) * DD * NN + q0;
    const float* Kg = g_k + (size_t)(b * HH + h) * DD * NN;
    __half* Sg = g_s + ((size_t)((b * HH + h) * NN) + q0) * NN;

    #pragma unroll
    for (int it = 0; it < 2; it++) {           // Qs: 64d x 32q, prescaled
        int e = tid + it * 256;
        int dd = e >> 3, q4 = (e & 7) * 4;
        float4 v = *(const float4*)&Qg[(size_t)dd * NN + q4];
        *(float4*)&Qs[dd * QS_STRIDE + q4] =
            make_float4(v.x * QSCALE, v.y * QSCALE, v.z * QSCALE, v.w * QSCALE);
    }

    float rowpart[8] = {0.f,0.f,0.f,0.f,0.f,0.f,0.f,0.f};

    for (int kt = 0; kt < 4; kt++) {
        int k0 = kt * 256;
        __syncthreads();
        #pragma unroll
        for (int it = 0; it < 16; it++) {      // Ks: 64d x 256k
            int e = tid + it * 256;
            int dd = e >> 6, r4 = (e & 63) * 4;
            float4 v = *(const float4*)&Kg[(size_t)dd * NN + k0 + r4];
            *(float4*)&Ks[dd * KS_STRIDE + r4] = v;
        }
        __syncthreads();

        unsigned long long acc[4][4];
        #pragma unroll
        for (int i = 0; i < 4; i++)
            #pragma unroll
            for (int j = 0; j < 4; j++) acc[i][j] = NEG4;

        #pragma unroll 8
        for (int kk = 0; kk < 64; kk++) {
            float4 a0 = *(const float4*)&Qs[kk * QS_STRIDE + qg];
            float4 a1 = *(const float4*)&Qs[kk * QS_STRIDE + qg + 4];
            float4 bv = *(const float4*)&Ks[kk * KS_STRIDE + kbase];
            unsigned long long A[4] = { f2pack(a0.x, a0.y), f2pack(a0.z, a0.w),
                                        f2pack(a1.x, a1.y), f2pack(a1.z, a1.w) };
            unsigned long long Bd[4] = { f2pack(bv.x, bv.x), f2pack(bv.y, bv.y),
                                         f2pack(bv.z, bv.z), f2pack(bv.w, bv.w) };
            #pragma unroll
            for (int qq = 0; qq < 4; qq++)
                #pragma unroll
                for (int kc = 0; kc < 4; kc++)
                    acc[qq][kc] = ffma2(A[qq], Bd[kc], acc[qq][kc]);
        }

        // e' = 2^(y-4); rowparts; STG 4 halves per row (unscaled)
        #pragma unroll
        for (int qq = 0; qq < 4; qq++) {
            float elo[4], ehi[4];
            float slo = 0.f, shi = 0.f;
            #pragma unroll
            for (int kc = 0; kc < 4; kc++) {
                float2 u = f2unpack(acc[qq][kc]);
                elo[kc] = ex2f(u.x); ehi[kc] = ex2f(u.y);
                slo += elo[kc]; shi += ehi[kc];
            }
            rowpart[2*qq]   += slo;
            rowpart[2*qq+1] += shi;
            uint2 plo = make_uint2(h2pack(elo[0], elo[1]), h2pack(elo[2], elo[3]));
            uint2 phi = make_uint2(h2pack(ehi[0], ehi[1]), h2pack(ehi[2], ehi[3]));
            *(uint2*)&Sg[(size_t)(qg + 2*qq)     * NN + k0 + kbase] = plo;
            *(uint2*)&Sg[(size_t)(qg + 2*qq + 1) * NN + k0 + kbase] = phi;
        }
    }

    #pragma unroll
    for (int i = 0; i < 8; i++) {
        float s = rowpart[i];
        #pragma unroll
        for (int o = 16; o; o >>= 1) s += __shfl_xor_sync(~0u, s, o);
        if (tx == 0) rpart[ks * 32 + qg + i] = s;
    }
    __syncthreads();
    if (tid < 32)
        g_rsinv[(b * HH + h) * NN + q0 + tid] = 1.f / (rpart[tid] + rpart[32 + tid]);
}

// ---------------------------------------------------------------------------
// Kernel 3: build fin = sum_h e_h*rinv_h (same fmaf order as before ->
// identical values), compute w2 = exp_small(fin/256) in regs, fp64 rowsum,
// normalize, per-block fp64 column partials in smem (8 deterministic phases),
// atomicAdd into g_ksc. g_attn / colsum eliminated.
// Block = 8 q rows (warp/row), grid 1024.
// ---------------------------------------------------------------------------
__global__ __launch_bounds__(256) void build_kernel() {
    __shared__ double colsum[1024];   // 8 KB
    int b  = blockIdx.x >> 7;
    int r0 = (blockIdx.x & 127) * 8;
    int w    = threadIdx.x >> 5;
    int lane = threadIdx.x & 31;
    int q = r0 + w;

    for (int i = threadIdx.x; i < 1024; i += 256) colsum[i] = 0.0;

    const __half* sp = g_s + ((size_t)(b * HH) * NN + q) * NN;
    float rinv8[8];
    #pragma unroll
    for (int h = 0; h < 8; h++) rinv8[h] = g_rsinv[(b * HH + h) * NN + q];

    float w2v[32];
    double s0 = 0.0, s1 = 0.0;
    #pragma unroll 2
    for (int c = 0; c < 16; c++) {
        int k = c * 64 + lane * 2;
        float a0 = 0.f, a1 = 0.f;
        #pragma unroll
        for (int h = 0; h < 8; h++) {
            __half2 hv = *(const __half2*)(sp + (size_t)h * NN * NN + k);
            float2 f = __half22float2(hv);
            a0 = fmaf(f.x, rinv8[h], a0);
            a1 = fmaf(f.y, rinv8[h], a1);
        }
        float e0 = exp_small_f(a0 * (1.f / 256.f));
        float e1 = exp_small_f(a1 * (1.f / 256.f));
        w2v[2*c]   = e0;
        w2v[2*c+1] = e1;
        s0 += (double)e0;
        s1 += (double)e1;
    }
    double ws = s0 + s1;
    #pragma unroll
    for (int o = 16; o; o >>= 1) ws += __shfl_xor_sync(~0u, ws, o);
    double rinv = 1.0 / ws;

    __syncthreads();   // colsum zeroed
    for (int ph = 0; ph < 8; ph++) {
        if (w == ph) {
            #pragma unroll
            for (int c = 0; c < 16; c++) {
                int k = c * 64 + lane * 2;
                colsum[k]     = fma((double)w2v[2*c],   rinv, colsum[k]);
                colsum[k + 1] = fma((double)w2v[2*c+1], rinv, colsum[k + 1]);
            }
        }
        __syncthreads();
    }
    for (int i = threadIdx.x; i < 1024; i += 256)
        atomicAdd(&g_ksc[b * NN + i], colsum[i] * (1.0 / 1024.0));
}

// ---------------------------------------------------------------------------
// Kernel 4: zero key_scores (split into 3 launches so proj is launch #4).
// ---------------------------------------------------------------------------
__global__ void zero_ks_kernel(int off) {
    g_ksc[off + blockIdx.x * 1024 + threadIdx.x] = 0.0;
}

// ---------------------------------------------------------------------------
// Kernel 5: top-8 per batch, fp32-quantized compares + lowest-index ties.
// ---------------------------------------------------------------------------
__global__ __launch_bounds__(256) void topk_kernel(const float* __restrict__ x) {
    __shared__ float bvv[8];
    __shared__ int   bii[8];
    __shared__ int   sel[8];
    __shared__ int   sbi;
    int b = blockIdx.x;
    int tid = threadIdx.x;
    int lane = tid & 31, warp = tid >> 5;

    float v[4]; int idx[4];
    #pragma unroll
    for (int j = 0; j < 4; j++) {
        idx[j] = tid + j * 256;
        v[j] = (float)g_ksc[b * NN + idx[j]];
    }

    for (int it = 0; it < 8; it++) {
        float mv = v[0]; int mi = idx[0];
        #pragma unroll
        for (int j = 1; j < 4; j++)
            if (v[j] > mv || (v[j] == mv && idx[j] < mi)) { mv = v[j]; mi = idx[j]; }
        #pragma unroll
        for (int o = 16; o; o >>= 1) {
            float ov = __shfl_xor_sync(~0u, mv, o);
            int   oi = __shfl_xor_sync(~0u, mi, o);
            if (ov > mv || (ov == mv && oi < mi)) { mv = ov; mi = oi; }
        }
        if (lane == 0) { bvv[warp] = mv; bii[warp] = mi; }
        __syncthreads();
        if (tid == 0) {
            float m2 = bvv[0]; int i2 = bii[0];
            for (int ww = 1; ww < 8; ww++)
                if (bvv[ww] > m2 || (bvv[ww] == m2 && bii[ww] < i2)) { m2 = bvv[ww]; i2 = bii[ww]; }
            sel[it] = i2; sbi = i2;
        }
        __syncthreads();
        int si = sbi;
        #pragma unroll
        for (int j = 0; j < 4; j++) if (idx[j] == si) v[j] = -CUDART_INF_F;
        __syncthreads();
    }

    for (int c = tid; c < CC; c += 256) {
        const float* xb = x + ((size_t)(b * CC + c)) * NN;
        float m = -CUDART_INF_F;
        #pragma unroll
        for (int j = 0; j < 8; j++) m = fmaxf(m, xb[sel[j]]);
        g_mp[b * CC + c] = m;
    }
}

// ---------------------------------------------------------------------------
// Kernel 6: out = x + max_pooled broadcast (float4)
// ---------------------------------------------------------------------------
__global__ void add_kernel(const float* __restrict__ x, float* __restrict__ out) {
    int i = blockIdx.x * 256 + threadIdx.x;
    int bc = i >> 8;
    float4 xv = ((const float4*)x)[i];
    float m = g_mp[bc];
    ((float4*)out)[i] = make_float4(xv.x + m, xv.y + m, xv.z + m, xv.w + m);
}

// ---------------------------------------------------------------------------
extern "C" void kernel_launch(void* const* d_in, const int* in_sizes, int n_in,
                              void* d_out, int out_size) {
    const float* x    = (const float*)d_in[0];
    const float* W    = (const float*)d_in[1];
    const float* bias = (const float*)d_in[2];
    float* out = (float*)d_out;

    cudaFuncSetAttribute(attn_kernel, cudaFuncAttributeMaxDynamicSharedMemorySize, SMEM2);

    zero_ks_kernel<<<2, 1024>>>(0);                    // launch 1
    zero_ks_kernel<<<2, 1024>>>(2048);                 // launch 2
    zero_ks_kernel<<<4, 1024>>>(4096);                 // launch 3
    proj_kernel<<<dim3(16, 64), 256>>>(x, W, bias);    // launch 4 (profiled)
    attn_kernel<<<2048, 256, SMEM2>>>();               // launch 5
    build_kernel<<<1024, 256>>>();                     // launch 6
    topk_kernel<<<8, 256>>>(x);                        // launch 7
    add_kernel<<<(BB * CC * NN) / 1024, 256>>>(x, out);// launch 8
}

// round 15
// speedup vs baseline: 1.0060x; 1.0060x over previous
#include <cuda_runtime.h>
#include <cuda_fp16.h>
#include <math_constants.h>

#define BB 8
#define CC 512
#define NN 1024
#define HH 8
#define DD 64

// Q/K stored d-major per (b,h):  g_q[((b*HH+h)*DD + d)*NN + n]
__device__ float  g_q[BB*HH*NN*DD];
__device__ float  g_k[BB*HH*NN*DD];
__device__ __half g_s[(size_t)BB*HH*NN*NN];  // 128 MB: unscaled exp'd scores
__device__ float  g_rsinv[BB*HH*NN];         // fp32 1/rowsum per (b,h,q)
__device__ float  g_attn[BB*NN*NN];          // head-summed attn
__device__ double g_rinv[BB*NN];             // 1 / row-sum of exp(attn/256)
__device__ double g_ksc[BB*NN];              // key_scores accumulators (fp64)
__device__ float  g_mp[BB*CC];               // max-pooled (B, C)

// ---- packed f32x2 helpers ---------------------------------------------------
__device__ __forceinline__ unsigned long long f2pack(float lo, float hi) {
    unsigned long long r;
    asm("mov.b64 %0, {%1, %2};" : "=l"(r) : "f"(lo), "f"(hi));
    return r;
}
__device__ __forceinline__ unsigned long long ffma2(unsigned long long a,
                                                    unsigned long long b,
                                                    unsigned long long c) {
    unsigned long long d;
    asm("fma.rn.f32x2 %0, %1, %2, %3;" : "=l"(d) : "l"(a), "l"(b), "l"(c));
    return d;
}
__device__ __forceinline__ float2 f2unpack(unsigned long long v) {
    float lo, hi;
    asm("mov.b64 {%0, %1}, %2;" : "=f"(lo), "=f"(hi) : "l"(v));
    return make_float2(lo, hi);
}
__device__ __forceinline__ float ex2f(float x) {
    float y;
    asm("ex2.approx.ftz.f32 %0, %1;" : "=f"(y) : "f"(x));
    return y;
}
// pack two fp32 into f16x2: lo half = first arg
__device__ __forceinline__ unsigned int h2pack(float lo, float hi) {
    unsigned int d;
    asm("cvt.rn.f16x2.f32 %0, %1, %2;" : "=r"(d) : "f"(hi), "f"(lo));
    return d;
}

// exp(x) for x in [0, 1/32], fp32 degree-4 Taylor (round-6 error budget).
__device__ __forceinline__ float exp_small_f(float x) {
    float p = 1.f / 24.f;
    p = fmaf(p, x, 1.f / 6.f);
    p = fmaf(p, x, 0.5f);
    p = fmaf(p, x, 1.f);
    p = fmaf(p, x, 1.f);
    return p;
}

// ---------------------------------------------------------------------------
// Kernel 1: fused Q/K projection. Tile 128m x 64j, microtile 8m x 4j.
// __launch_bounds__(256,3): 3 blocks/SM (24 warps) to hide LDS latency;
// staging loops unroll-limited to shed hoisted address registers.
// ---------------------------------------------------------------------------
__global__ __launch_bounds__(256, 3) void proj_kernel(const float* __restrict__ x,
                                                      const float* __restrict__ W,
                                                      const float* __restrict__ bias) {
    __shared__ float As[16 * 132];
    __shared__ float Bs[16 * 68];
    int tid = threadIdx.x;
    int tx  = tid & 31;
    int wid = tid >> 5;
    int jq  = tx & 15;
    int mg  = wid * 2 + (tx >> 4);
    int j0 = blockIdx.x * 64;
    int m0 = blockIdx.y * 128;
    int b  = m0 >> 10;
    int n0 = m0 & 1023;
    const float* xb = x + (size_t)b * CC * NN;

    unsigned long long acc[4][4];
    #pragma unroll
    for (int i = 0; i < 4; i++)
        #pragma unroll
        for (int j = 0; j < 4; j++) acc[i][j] = 0ull;

    for (int kb = 0; kb < CC; kb += 16) {
        #pragma unroll 4
        for (int p = 0; p < 8; p++) {
            int e = tid + p * 256;
            int kk = e >> 7, mm = e & 127;
            As[kk * 132 + mm] = xb[(kb + kk) * NN + n0 + mm];
        }
        #pragma unroll 2
        for (int p = 0; p < 4; p++) {
            int e = tid + p * 256;
            int kk = e & 15, jl = e >> 4;
            Bs[kk * 68 + jl] = W[(size_t)(j0 + jl) * CC + kb + kk];
        }
        __syncthreads();
        #pragma unroll
        for (int kk = 0; kk < 16; kk++) {
            float4 a0 = *(const float4*)&As[kk * 132 + mg * 8];
            float4 a1 = *(const float4*)&As[kk * 132 + mg * 8 + 4];
            float4 bq = *(const float4*)&Bs[kk * 68 + 4 * jq];
            unsigned long long A[4] = { f2pack(a0.x, a0.y), f2pack(a0.z, a0.w),
                                        f2pack(a1.x, a1.y), f2pack(a1.z, a1.w) };
            unsigned long long Bd[4] = { f2pack(bq.x, bq.x), f2pack(bq.y, bq.y),
                                         f2pack(bq.z, bq.z), f2pack(bq.w, bq.w) };
            #pragma unroll
            for (int am = 0; am < 4; am++)
                #pragma unroll
                for (int j = 0; j < 4; j++)
                    acc[am][j] = ffma2(A[am], Bd[j], acc[am][j]);
        }
        __syncthreads();
    }

    #pragma unroll
    for (int j = 0; j < 4; j++) {
        int jg = j0 + 4 * jq + j;
        float bsv = bias[jg];
        int head = (jg & 511) >> 6;
        int dd   = jg & 63;
        float* dst = ((jg < 512) ? g_q : g_k)
                   + ((size_t)(b * HH + head) * DD + dd) * NN + n0 + mg * 8;
        float2 u0 = f2unpack(acc[0][j]);
        float2 u1 = f2unpack(acc[1][j]);
        float2 u2 = f2unpack(acc[2][j]);
        float2 u3 = f2unpack(acc[3][j]);
        *(float4*)&dst[0] = make_float4(u0.x + bsv, u0.y + bsv, u1.x + bsv, u1.y + bsv);
        *(float4*)&dst[4] = make_float4(u2.x + bsv, u2.y + bsv, u3.x + bsv, u3.y + bsv);
    }
}

// ---------------------------------------------------------------------------
// Kernel 2: per-(b,h,32q) exp'd scores -> g_s (fp16, unscaled) + 1/rowsum.
// (R13 version, known good: 3 blocks/SM, 8q x 4k microtile.)
// ---------------------------------------------------------------------------
#define QS_STRIDE 36
#define KS_STRIDE 260
#define SM_QS   0
#define SM_KS   (64*QS_STRIDE)
#define SM_RP   (SM_KS + 64*KS_STRIDE)
#define SMEM2   ((SM_RP + 64) * 4)

__global__ __launch_bounds__(256, 3) void attn_kernel() {
    extern __shared__ float sm[];
    float* Qs    = sm + SM_QS;     // [64 d][36: 32q + pad]
    float* Ks    = sm + SM_KS;     // [64 d][260: 256k + pad]
    float* rpart = sm + SM_RP;     // [2 strips][32 rows]

    const float QSCALE = 0.18033688f;          // log2(e)/8
    int tid = threadIdx.x;
    int b  = blockIdx.x >> 8;
    int h  = (blockIdx.x >> 5) & 7;
    int q0 = (blockIdx.x & 31) << 5;
    int tx = tid & 31, w = tid >> 5;
    int qg = (w & 3) * 8;
    int ks = w >> 2;
    int kbase = ks * 128 + 4 * tx;
    const unsigned long long NEG4 = f2pack(-4.f, -4.f);

    const float* Qg = g_q + (size_t)(b * HH + h) * DD * NN + q0;
    const float* Kg = g_k + (size_t)(b * HH + h) * DD * NN;
    __half* Sg = g_s + ((size_t)((b * HH + h) * NN) + q0) * NN;

    #pragma unroll
    for (int it = 0; it < 2; it++) {           // Qs: 64d x 32q, prescaled
        int e = tid + it * 256;
        int dd = e >> 3, q4 = (e & 7) * 4;
        float4 v = *(const float4*)&Qg[(size_t)dd * NN + q4];
        *(float4*)&Qs[dd * QS_STRIDE + q4] =
            make_float4(v.x * QSCALE, v.y * QSCALE, v.z * QSCALE, v.w * QSCALE);
    }

    float rowpart[8] = {0.f,0.f,0.f,0.f,0.f,0.f,0.f,0.f};

    for (int kt = 0; kt < 4; kt++) {
        int k0 = kt * 256;
        __syncthreads();
        #pragma unroll
        for (int it = 0; it < 16; it++) {      // Ks: 64d x 256k
            int e = tid + it * 256;
            int dd = e >> 6, r4 = (e & 63) * 4;
            float4 v = *(const float4*)&Kg[(size_t)dd * NN + k0 + r4];
            *(float4*)&Ks[dd * KS_STRIDE + r4] = v;
        }
        __syncthreads();

        unsigned long long acc[4][4];
        #pragma unroll
        for (int i = 0; i < 4; i++)
            #pragma unroll
            for (int j = 0; j < 4; j++) acc[i][j] = NEG4;

        #pragma unroll 8
        for (int kk = 0; kk < 64; kk++) {
            float4 a0 = *(const float4*)&Qs[kk * QS_STRIDE + qg];
            float4 a1 = *(const float4*)&Qs[kk * QS_STRIDE + qg + 4];
            float4 bv = *(const float4*)&Ks[kk * KS_STRIDE + kbase];
            unsigned long long A[4] = { f2pack(a0.x, a0.y), f2pack(a0.z, a0.w),
                                        f2pack(a1.x, a1.y), f2pack(a1.z, a1.w) };
            unsigned long long Bd[4] = { f2pack(bv.x, bv.x), f2pack(bv.y, bv.y),
                                         f2pack(bv.z, bv.z), f2pack(bv.w, bv.w) };
            #pragma unroll
            for (int qq = 0; qq < 4; qq++)
                #pragma unroll
                for (int kc = 0; kc < 4; kc++)
                    acc[qq][kc] = ffma2(A[qq], Bd[kc], acc[qq][kc]);
        }

        // e' = 2^(y-4); rowparts; STG 4 halves per row (unscaled)
        #pragma unroll
        for (int qq = 0; qq < 4; qq++) {
            float elo[4], ehi[4];
            float slo = 0.f, shi = 0.f;
            #pragma unroll
            for (int kc = 0; kc < 4; kc++) {
                float2 u = f2unpack(acc[qq][kc]);
                elo[kc] = ex2f(u.x); ehi[kc] = ex2f(u.y);
                slo += elo[kc]; shi += ehi[kc];
            }
            rowpart[2*qq]   += slo;
            rowpart[2*qq+1] += shi;
            uint2 plo = make_uint2(h2pack(elo[0], elo[1]), h2pack(elo[2], elo[3]));
            uint2 phi = make_uint2(h2pack(ehi[0], ehi[1]), h2pack(ehi[2], ehi[3]));
            *(uint2*)&Sg[(size_t)(qg + 2*qq)     * NN + k0 + kbase] = plo;
            *(uint2*)&Sg[(size_t)(qg + 2*qq + 1) * NN + k0 + kbase] = phi;
        }
    }

    #pragma unroll
    for (int i = 0; i < 8; i++) {
        float s = rowpart[i];
        #pragma unroll
        for (int o = 16; o; o >>= 1) s += __shfl_xor_sync(~0u, s, o);
        if (tx == 0) rpart[ks * 32 + qg + i] = s;
    }
    __syncthreads();
    if (tid < 32)
        g_rsinv[(b * HH + h) * NN + q0 + tid] = 1.f / (rpart[tid] + rpart[32 + tid]);
}

// ---------------------------------------------------------------------------
// Kernel 3: build attn = sum_h e_h * rinv_h (R13 version, known good),
// write g_attn + fp64 w2 rowsum -> g_rinv. Warp per q-row, barrier-free.
// ---------------------------------------------------------------------------
__global__ __launch_bounds__(256) void build_kernel() {
    int row  = blockIdx.x * 8 + (threadIdx.x >> 5);   // b*1024 + q
    int lane = threadIdx.x & 31;
    int b = row >> 10;
    int q = row & 1023;

    const __half* sp = g_s + ((size_t)(b * HH) * NN + q) * NN;
    float rinv8[8];
    #pragma unroll
    for (int h = 0; h < 8; h++) rinv8[h] = g_rsinv[(b * HH + h) * NN + q];

    float* gp = g_attn + (size_t)row * NN;
    double w0 = 0.0, w1 = 0.0;
    #pragma unroll 2
    for (int c = 0; c < 16; c++) {
        int k = c * 64 + lane * 2;
        float a0 = 0.f, a1 = 0.f;
        #pragma unroll
        for (int h = 0; h < 8; h++) {
            __half2 hv = *(const __half2*)(sp + (size_t)h * NN * NN + k);
            float2 f = __half22float2(hv);
            a0 = fmaf(f.x, rinv8[h], a0);
            a1 = fmaf(f.y, rinv8[h], a1);
        }
        *(float2*)&gp[k] = make_float2(a0, a1);
        w0 += (double)exp_small_f(a0 * (1.f / 256.f));
        w1 += (double)exp_small_f(a1 * (1.f / 256.f));
    }
    double ws = w0 + w1;
    #pragma unroll
    for (int o = 16; o; o >>= 1) ws += __shfl_xor_sync(~0u, ws, o);
    if (lane == 0) g_rinv[row] = 1.0 / ws;
}

// ---------------------------------------------------------------------------
// Kernel 4: column accumulation (R6 version). 16-row chunks, 4 cols/thread.
// ---------------------------------------------------------------------------
__global__ void zero_ks_kernel(int off) {
    g_ksc[off + blockIdx.x * 1024 + threadIdx.x] = 0.0;
}

__global__ __launch_bounds__(256) void colsum_kernel() {
    int b  = blockIdx.x >> 6;
    int q0 = (blockIdx.x & 63) << 4;
    int tid = threadIdx.x;
    const float* base = g_attn + ((size_t)b * NN + q0) * NN;
    const double* rinv = g_rinv + b * NN + q0;

    double acc[4] = {0.0, 0.0, 0.0, 0.0};
    #pragma unroll 4
    for (int q = 0; q < 16; q++) {
        const float* row = base + (size_t)q * NN;
        double inv = rinv[q];
        float e[4];
        #pragma unroll
        for (int j = 0; j < 4; j++) e[j] = exp_small_f(row[tid + j * 256] * (1.f / 256.f));
        #pragma unroll
        for (int j = 0; j < 4; j++) acc[j] = fma((double)e[j], inv, acc[j]);
    }
    #pragma unroll
    for (int j = 0; j < 4; j++)
        atomicAdd(&g_ksc[b * NN + tid + j * 256], acc[j] * (1.0 / 1024.0));
}

// ---------------------------------------------------------------------------
// Kernel 5: top-8 per batch, fp32-quantized compares + lowest-index ties.
// ---------------------------------------------------------------------------
__global__ __launch_bounds__(256) void topk_kernel(const float* __restrict__ x) {
    __shared__ float bvv[8];
    __shared__ int   bii[8];
    __shared__ int   sel[8];
    __shared__ int   sbi;
    int b = blockIdx.x;
    int tid = threadIdx.x;
    int lane = tid & 31, warp = tid >> 5;

    float v[4]; int idx[4];
    #pragma unroll
    for (int j = 0; j < 4; j++) {
        idx[j] = tid + j * 256;
        v[j] = (float)g_ksc[b * NN + idx[j]];
    }

    for (int it = 0; it < 8; it++) {
        float mv = v[0]; int mi = idx[0];
        #pragma unroll
        for (int j = 1; j < 4; j++)
            if (v[j] > mv || (v[j] == mv && idx[j] < mi)) { mv = v[j]; mi = idx[j]; }
        #pragma unroll
        for (int o = 16; o; o >>= 1) {
            float ov = __shfl_xor_sync(~0u, mv, o);
            int   oi = __shfl_xor_sync(~0u, mi, o);
            if (ov > mv || (ov == mv && oi < mi)) { mv = ov; mi = oi; }
        }
        if (lane == 0) { bvv[warp] = mv; bii[warp] = mi; }
        __syncthreads();
        if (tid == 0) {
            float m2 = bvv[0]; int i2 = bii[0];
            for (int ww = 1; ww < 8; ww++)
                if (bvv[ww] > m2 || (bvv[ww] == m2 && bii[ww] < i2)) { m2 = bvv[ww]; i2 = bii[ww]; }
            sel[it] = i2; sbi = i2;
        }
        __syncthreads();
        int si = sbi;
        #pragma unroll
        for (int j = 0; j < 4; j++) if (idx[j] == si) v[j] = -CUDART_INF_F;
        __syncthreads();
    }

    for (int c = tid; c < CC; c += 256) {
        const float* xb = x + ((size_t)(b * CC + c)) * NN;
        float m = -CUDART_INF_F;
        #pragma unroll
        for (int j = 0; j < 8; j++) m = fmaxf(m, xb[sel[j]]);
        g_mp[b * CC + c] = m;
    }
}

// ---------------------------------------------------------------------------
// Kernel 6: out = x + max_pooled broadcast (float4)
// ---------------------------------------------------------------------------
__global__ void add_kernel(const float* __restrict__ x, float* __restrict__ out) {
    int i = blockIdx.x * 256 + threadIdx.x;
    int bc = i >> 8;
    float4 xv = ((const float4*)x)[i];
    float m = g_mp[bc];
    ((float4*)out)[i] = make_float4(xv.x + m, xv.y + m, xv.z + m, xv.w + m);
}

// ---------------------------------------------------------------------------
extern "C" void kernel_launch(void* const* d_in, const int* in_sizes, int n_in,
                              void* d_out, int out_size) {
    const float* x    = (const float*)d_in[0];
    const float* W    = (const float*)d_in[1];
    const float* bias = (const float*)d_in[2];
    float* out = (float*)d_out;

    cudaFuncSetAttribute(attn_kernel, cudaFuncAttributeMaxDynamicSharedMemorySize, SMEM2);

    zero_ks_kernel<<<2, 1024>>>(0);                    // launch 1
    zero_ks_kernel<<<2, 1024>>>(2048);                 // launch 2
    zero_ks_kernel<<<4, 1024>>>(4096);                 // launch 3
    proj_kernel<<<dim3(16, 64), 256>>>(x, W, bias);    // launch 4 (profiled)
    attn_kernel<<<2048, 256, SMEM2>>>();               // launch 5
    build_kernel<<<1024, 256>>>();                     // launch 6
    colsum_kernel<<<512, 256>>>();                     // launch 7
    topk_kernel<<<8, 256>>>(x);                        // launch 8
    add_kernel<<<(BB * CC * NN) / 1024, 256>>>(x, out);// launch 9
}

// round 16
// speedup vs baseline: 1.0728x; 1.0664x over previous
#include <cuda_runtime.h>
#include <cuda_fp16.h>
#include <math_constants.h>

#define BB 8
#define CC 512
#define NN 1024
#define HH 8
#define DD 64

// Q/K stored d-major per (b,h):  g_q[((b*HH+h)*DD + d)*NN + n]
__device__ float  g_q[BB*HH*NN*DD];
__device__ float  g_k[BB*HH*NN*DD];
__device__ __half g_s[(size_t)BB*HH*NN*NN];  // 128 MB: unscaled exp'd scores
__device__ float  g_rsinv[BB*HH*NN];         // fp32 1/rowsum per (b,h,q)
__device__ float  g_attn[BB*NN*NN];          // head-summed attn
__device__ double g_rinv[BB*NN];             // 1 / row-sum of exp(attn/256)
__device__ double g_ksc[BB*NN];              // key_scores accumulators (fp64)
__device__ float  g_mp[BB*CC];               // max-pooled (B, C)

// ---- packed f32x2 helpers ---------------------------------------------------
__device__ __forceinline__ unsigned long long f2pack(float lo, float hi) {
    unsigned long long r;
    asm("mov.b64 %0, {%1, %2};" : "=l"(r) : "f"(lo), "f"(hi));
    return r;
}
__device__ __forceinline__ unsigned long long ffma2(unsigned long long a,
                                                    unsigned long long b,
                                                    unsigned long long c) {
    unsigned long long d;
    asm("fma.rn.f32x2 %0, %1, %2, %3;" : "=l"(d) : "l"(a), "l"(b), "l"(c));
    return d;
}
__device__ __forceinline__ float2 f2unpack(unsigned long long v) {
    float lo, hi;
    asm("mov.b64 {%0, %1}, %2;" : "=f"(lo), "=f"(hi) : "l"(v));
    return make_float2(lo, hi);
}
__device__ __forceinline__ float ex2f(float x) {
    float y;
    asm("ex2.approx.ftz.f32 %0, %1;" : "=f"(y) : "f"(x));
    return y;
}
// pack two fp32 into f16x2: lo half = first arg
__device__ __forceinline__ unsigned int h2pack(float lo, float hi) {
    unsigned int d;
    asm("cvt.rn.f16x2.f32 %0, %1, %2;" : "=r"(d) : "f"(hi), "f"(lo));
    return d;
}
// 4-byte async copy global->shared
__device__ __forceinline__ void cp_async4(unsigned int saddr, const float* g) {
    asm volatile("cp.async.ca.shared.global [%0], [%1], 4;" :: "r"(saddr), "l"(g));
}

// exp(x) for x in [0, 1/32], fp32 degree-4 Taylor (round-6 error budget).
__device__ __forceinline__ float exp_small_f(float x) {
    float p = 1.f / 24.f;
    p = fmaf(p, x, 1.f / 6.f);
    p = fmaf(p, x, 0.5f);
    p = fmaf(p, x, 1.f);
    p = fmaf(p, x, 1.f);
    return p;
}

// ---------------------------------------------------------------------------
// Kernel 1: fused Q/K projection. Tile 128m x 64j, microtile 8m x 4j.
// cp.async double-buffered staging: tile i+1 loads overlap tile i compute.
// ---------------------------------------------------------------------------
#define AS_STRIDE 132
#define AS_BUF    (16 * AS_STRIDE)   // 2112 floats
#define BS_STRIDE 68
#define BS_BUF    (16 * BS_STRIDE)   // 1088 floats

__global__ __launch_bounds__(256) void proj_kernel(const float* __restrict__ x,
                                                   const float* __restrict__ W,
                                                   const float* __restrict__ bias) {
    __shared__ float As[2 * AS_BUF];
    __shared__ float Bs[2 * BS_BUF];
    int tid = threadIdx.x;
    int tx  = tid & 31;
    int wid = tid >> 5;
    int jq  = tx & 15;
    int mg  = wid * 2 + (tx >> 4);
    int j0 = blockIdx.x * 64;
    int m0 = blockIdx.y * 128;
    int b  = m0 >> 10;
    int n0 = m0 & 1023;
    const float* xb = x + (size_t)b * CC * NN;

    unsigned int as_base = (unsigned int)__cvta_generic_to_shared(As);
    unsigned int bs_base = (unsigned int)__cvta_generic_to_shared(Bs);

    // per-thread staging indices
    int akk = tid >> 7;            // base kk for As (p adds 2 each)
    int amm = tid & 127;
    int bkk = tid & 15;
    int bjl = tid >> 4;            // base jl (p adds 16 each)

    unsigned long long acc[4][4];
    #pragma unroll
    for (int i = 0; i < 4; i++)
        #pragma unroll
        for (int j = 0; j < 4; j++) acc[i][j] = 0ull;

    // issue k-tile 0 into buffer 0
    #pragma unroll
    for (int p = 0; p < 8; p++) {
        int kk = akk + p * 2;
        cp_async4(as_base + (unsigned)(kk * AS_STRIDE + amm) * 4,
                  &xb[kk * NN + n0 + amm]);
    }
    #pragma unroll
    for (int p = 0; p < 4; p++) {
        int jl = bjl + p * 16;
        cp_async4(bs_base + (unsigned)(bkk * BS_STRIDE + jl) * 4,
                  &W[(size_t)(j0 + jl) * CC + bkk]);
    }
    asm volatile("cp.async.commit_group;");

    for (int i = 0; i < 32; i++) {
        int buf = i & 1;
        if (i < 31) {
            int kb = (i + 1) * 16;
            int nbuf = 1 - buf;
            #pragma unroll
            for (int p = 0; p < 8; p++) {
                int kk = akk + p * 2;
                cp_async4(as_base + (unsigned)(nbuf * AS_BUF + kk * AS_STRIDE + amm) * 4,
                          &xb[(kb + kk) * NN + n0 + amm]);
            }
            #pragma unroll
            for (int p = 0; p < 4; p++) {
                int jl = bjl + p * 16;
                cp_async4(bs_base + (unsigned)(nbuf * BS_BUF + bkk * BS_STRIDE + jl) * 4,
                          &W[(size_t)(j0 + jl) * CC + kb + bkk]);
            }
            asm volatile("cp.async.commit_group;");
            asm volatile("cp.async.wait_group 1;");
        } else {
            asm volatile("cp.async.wait_group 0;");
        }
        __syncthreads();

        const float* Asb = As + buf * AS_BUF;
        const float* Bsb = Bs + buf * BS_BUF;
        #pragma unroll
        for (int kk = 0; kk < 16; kk++) {
            float4 a0 = *(const float4*)&Asb[kk * AS_STRIDE + mg * 8];
            float4 a1 = *(const float4*)&Asb[kk * AS_STRIDE + mg * 8 + 4];
            float4 bq = *(const float4*)&Bsb[kk * BS_STRIDE + 4 * jq];
            unsigned long long A[4] = { f2pack(a0.x, a0.y), f2pack(a0.z, a0.w),
                                        f2pack(a1.x, a1.y), f2pack(a1.z, a1.w) };
            unsigned long long Bd[4] = { f2pack(bq.x, bq.x), f2pack(bq.y, bq.y),
                                         f2pack(bq.z, bq.z), f2pack(bq.w, bq.w) };
            #pragma unroll
            for (int am = 0; am < 4; am++)
                #pragma unroll
                for (int j = 0; j < 4; j++)
                    acc[am][j] = ffma2(A[am], Bd[j], acc[am][j]);
        }
        __syncthreads();
    }

    #pragma unroll
    for (int j = 0; j < 4; j++) {
        int jg = j0 + 4 * jq + j;
        float bsv = bias[jg];
        int head = (jg & 511) >> 6;
        int dd   = jg & 63;
        float* dst = ((jg < 512) ? g_q : g_k)
                   + ((size_t)(b * HH + head) * DD + dd) * NN + n0 + mg * 8;
        float2 u0 = f2unpack(acc[0][j]);
        float2 u1 = f2unpack(acc[1][j]);
        float2 u2 = f2unpack(acc[2][j]);
        float2 u3 = f2unpack(acc[3][j]);
        *(float4*)&dst[0] = make_float4(u0.x + bsv, u0.y + bsv, u1.x + bsv, u1.y + bsv);
        *(float4*)&dst[4] = make_float4(u2.x + bsv, u2.y + bsv, u3.x + bsv, u3.y + bsv);
    }
}

// ---------------------------------------------------------------------------
// Kernel 2: per-(b,h,32q) exp'd scores -> g_s (fp16, unscaled) + 1/rowsum.
// (R13 version, known good: 3 blocks/SM, 8q x 4k microtile.)
// ---------------------------------------------------------------------------
#define QS_STRIDE 36
#define KS_STRIDE 260
#define SM_QS   0
#define SM_KS   (64*QS_STRIDE)
#define SM_RP   (SM_KS + 64*KS_STRIDE)
#define SMEM2   ((SM_RP + 64) * 4)

__global__ __launch_bounds__(256, 3) void attn_kernel() {
    extern __shared__ float sm[];
    float* Qs    = sm + SM_QS;     // [64 d][36: 32q + pad]
    float* Ks    = sm + SM_KS;     // [64 d][260: 256k + pad]
    float* rpart = sm + SM_RP;     // [2 strips][32 rows]

    const float QSCALE = 0.18033688f;          // log2(e)/8
    int tid = threadIdx.x;
    int b  = blockIdx.x >> 8;
    int h  = (blockIdx.x >> 5) & 7;
    int q0 = (blockIdx.x & 31) << 5;
    int tx = tid & 31, w = tid >> 5;
    int qg = (w & 3) * 8;
    int ks = w >> 2;
    int kbase = ks * 128 + 4 * tx;
    const unsigned long long NEG4 = f2pack(-4.f, -4.f);

    const float* Qg = g_q + (size_t)(b * HH + h) * DD * NN + q0;
    const float* Kg = g_k + (size_t)(b * HH + h) * DD * NN;
    __half* Sg = g_s + ((size_t)((b * HH + h) * NN) + q0) * NN;

    #pragma unroll
    for (int it = 0; it < 2; it++) {           // Qs: 64d x 32q, prescaled
        int e = tid + it * 256;
        int dd = e >> 3, q4 = (e & 7) * 4;
        float4 v = *(const float4*)&Qg[(size_t)dd * NN + q4];
        *(float4*)&Qs[dd * QS_STRIDE + q4] =
            make_float4(v.x * QSCALE, v.y * QSCALE, v.z * QSCALE, v.w * QSCALE);
    }

    float rowpart[8] = {0.f,0.f,0.f,0.f,0.f,0.f,0.f,0.f};

    for (int kt = 0; kt < 4; kt++) {
        int k0 = kt * 256;
        __syncthreads();
        #pragma unroll
        for (int it = 0; it < 16; it++) {      // Ks: 64d x 256k
            int e = tid + it * 256;
            int dd = e >> 6, r4 = (e & 63) * 4;
            float4 v = *(const float4*)&Kg[(size_t)dd * NN + k0 + r4];
            *(float4*)&Ks[dd * KS_STRIDE + r4] = v;
        }
        __syncthreads();

        unsigned long long acc[4][4];
        #pragma unroll
        for (int i = 0; i < 4; i++)
            #pragma unroll
            for (int j = 0; j < 4; j++) acc[i][j] = NEG4;

        #pragma unroll 8
        for (int kk = 0; kk < 64; kk++) {
            float4 a0 = *(const float4*)&Qs[kk * QS_STRIDE + qg];
            float4 a1 = *(const float4*)&Qs[kk * QS_STRIDE + qg + 4];
            float4 bv = *(const float4*)&Ks[kk * KS_STRIDE + kbase];
            unsigned long long A[4] = { f2pack(a0.x, a0.y), f2pack(a0.z, a0.w),
                                        f2pack(a1.x, a1.y), f2pack(a1.z, a1.w) };
            unsigned long long Bd[4] = { f2pack(bv.x, bv.x), f2pack(bv.y, bv.y),
                                         f2pack(bv.z, bv.z), f2pack(bv.w, bv.w) };
            #pragma unroll
            for (int qq = 0; qq < 4; qq++)
                #pragma unroll
                for (int kc = 0; kc < 4; kc++)
                    acc[qq][kc] = ffma2(A[qq], Bd[kc], acc[qq][kc]);
        }

        // e' = 2^(y-4); rowparts; STG 4 halves per row (unscaled)
        #pragma unroll
        for (int qq = 0; qq < 4; qq++) {
            float elo[4], ehi[4];
            float slo = 0.f, shi = 0.f;
            #pragma unroll
            for (int kc = 0; kc < 4; kc++) {
                float2 u = f2unpack(acc[qq][kc]);
                elo[kc] = ex2f(u.x); ehi[kc] = ex2f(u.y);
                slo += elo[kc]; shi += ehi[kc];
            }
            rowpart[2*qq]   += slo;
            rowpart[2*qq+1] += shi;
            uint2 plo = make_uint2(h2pack(elo[0], elo[1]), h2pack(elo[2], elo[3]));
            uint2 phi = make_uint2(h2pack(ehi[0], ehi[1]), h2pack(ehi[2], ehi[3]));
            *(uint2*)&Sg[(size_t)(qg + 2*qq)     * NN + k0 + kbase] = plo;
            *(uint2*)&Sg[(size_t)(qg + 2*qq + 1) * NN + k0 + kbase] = phi;
        }
    }

    #pragma unroll
    for (int i = 0; i < 8; i++) {
        float s = rowpart[i];
        #pragma unroll
        for (int o = 16; o; o >>= 1) s += __shfl_xor_sync(~0u, s, o);
        if (tx == 0) rpart[ks * 32 + qg + i] = s;
    }
    __syncthreads();
    if (tid < 32)
        g_rsinv[(b * HH + h) * NN + q0 + tid] = 1.f / (rpart[tid] + rpart[32 + tid]);
}

// ---------------------------------------------------------------------------
// Kernel 3: build attn = sum_h e_h * rinv_h (R13 version, known good),
// write g_attn + fp64 w2 rowsum -> g_rinv. Warp per q-row, barrier-free.
// ---------------------------------------------------------------------------
__global__ __launch_bounds__(256) void build_kernel() {
    int row  = blockIdx.x * 8 + (threadIdx.x >> 5);   // b*1024 + q
    int lane = threadIdx.x & 31;
    int b = row >> 10;
    int q = row & 1023;

    const __half* sp = g_s + ((size_t)(b * HH) * NN + q) * NN;
    float rinv8[8];
    #pragma unroll
    for (int h = 0; h < 8; h++) rinv8[h] = g_rsinv[(b * HH + h) * NN + q];

    float* gp = g_attn + (size_t)row * NN;
    double w0 = 0.0, w1 = 0.0;
    #pragma unroll 2
    for (int c = 0; c < 16; c++) {
        int k = c * 64 + lane * 2;
        float a0 = 0.f, a1 = 0.f;
        #pragma unroll
        for (int h = 0; h < 8; h++) {
            __half2 hv = *(const __half2*)(sp + (size_t)h * NN * NN + k);
            float2 f = __half22float2(hv);
            a0 = fmaf(f.x, rinv8[h], a0);
            a1 = fmaf(f.y, rinv8[h], a1);
        }
        *(float2*)&gp[k] = make_float2(a0, a1);
        w0 += (double)exp_small_f(a0 * (1.f / 256.f));
        w1 += (double)exp_small_f(a1 * (1.f / 256.f));
    }
    double ws = w0 + w1;
    #pragma unroll
    for (int o = 16; o; o >>= 1) ws += __shfl_xor_sync(~0u, ws, o);
    if (lane == 0) g_rinv[row] = 1.0 / ws;
}

// ---------------------------------------------------------------------------
// Kernel 4: column accumulation (R6 version). 16-row chunks, 4 cols/thread.
// ---------------------------------------------------------------------------
__global__ void zero_ks_kernel(int off) {
    g_ksc[off + blockIdx.x * 1024 + threadIdx.x] = 0.0;
}

__global__ __launch_bounds__(256) void colsum_kernel() {
    int b  = blockIdx.x >> 6;
    int q0 = (blockIdx.x & 63) << 4;
    int tid = threadIdx.x;
    const float* base = g_attn + ((size_t)b * NN + q0) * NN;
    const double* rinv = g_rinv + b * NN + q0;

    double acc[4] = {0.0, 0.0, 0.0, 0.0};
    #pragma unroll 4
    for (int q = 0; q < 16; q++) {
        const float* row = base + (size_t)q * NN;
        double inv = rinv[q];
        float e[4];
        #pragma unroll
        for (int j = 0; j < 4; j++) e[j] = exp_small_f(row[tid + j * 256] * (1.f / 256.f));
        #pragma unroll
        for (int j = 0; j < 4; j++) acc[j] = fma((double)e[j], inv, acc[j]);
    }
    #pragma unroll
    for (int j = 0; j < 4; j++)
        atomicAdd(&g_ksc[b * NN + tid + j * 256], acc[j] * (1.0 / 1024.0));
}

// ---------------------------------------------------------------------------
// Kernel 5: top-8 per batch, fp32-quantized compares + lowest-index ties.
// ---------------------------------------------------------------------------
__global__ __launch_bounds__(256) void topk_kernel(const float* __restrict__ x) {
    __shared__ float bvv[8];
    __shared__ int   bii[8];
    __shared__ int   sel[8];
    __shared__ int   sbi;
    int b = blockIdx.x;
    int tid = threadIdx.x;
    int lane = tid & 31, warp = tid >> 5;

    float v[4]; int idx[4];
    #pragma unroll
    for (int j = 0; j < 4; j++) {
        idx[j] = tid + j * 256;
        v[j] = (float)g_ksc[b * NN + idx[j]];
    }

    for (int it = 0; it < 8; it++) {
        float mv = v[0]; int mi = idx[0];
        #pragma unroll
        for (int j = 1; j < 4; j++)
            if (v[j] > mv || (v[j] == mv && idx[j] < mi)) { mv = v[j]; mi = idx[j]; }
        #pragma unroll
        for (int o = 16; o; o >>= 1) {
            float ov = __shfl_xor_sync(~0u, mv, o);
            int   oi = __shfl_xor_sync(~0u, mi, o);
            if (ov > mv || (ov == mv && oi < mi)) { mv = ov; mi = oi; }
        }
        if (lane == 0) { bvv[warp] = mv; bii[warp] = mi; }
        __syncthreads();
        if (tid == 0) {
            float m2 = bvv[0]; int i2 = bii[0];
            for (int ww = 1; ww < 8; ww++)
                if (bvv[ww] > m2 || (bvv[ww] == m2 && bii[ww] < i2)) { m2 = bvv[ww]; i2 = bii[ww]; }
            sel[it] = i2; sbi = i2;
        }
        __syncthreads();
        int si = sbi;
        #pragma unroll
        for (int j = 0; j < 4; j++) if (idx[j] == si) v[j] = -CUDART_INF_F;
        __syncthreads();
    }

    for (int c = tid; c < CC; c += 256) {
        const float* xb = x + ((size_t)(b * CC + c)) * NN;
        float m = -CUDART_INF_F;
        #pragma unroll
        for (int j = 0; j < 8; j++) m = fmaxf(m, xb[sel[j]]);
        g_mp[b * CC + c] = m;
    }
}

// ---------------------------------------------------------------------------
// Kernel 6: out = x + max_pooled broadcast (float4)
// ---------------------------------------------------------------------------
__global__ void add_kernel(const float* __restrict__ x, float* __restrict__ out) {
    int i = blockIdx.x * 256 + threadIdx.x;
    int bc = i >> 8;
    float4 xv = ((const float4*)x)[i];
    float m = g_mp[bc];
    ((float4*)out)[i] = make_float4(xv.x + m, xv.y + m, xv.z + m, xv.w + m);
}

// ---------------------------------------------------------------------------
extern "C" void kernel_launch(void* const* d_in, const int* in_sizes, int n_in,
                              void* d_out, int out_size) {
    const float* x    = (const float*)d_in[0];
    const float* W    = (const float*)d_in[1];
    const float* bias = (const float*)d_in[2];
    float* out = (float*)d_out;

    cudaFuncSetAttribute(attn_kernel, cudaFuncAttributeMaxDynamicSharedMemorySize, SMEM2);

    zero_ks_kernel<<<2, 1024>>>(0);                    // launch 1
    zero_ks_kernel<<<2, 1024>>>(2048);                 // launch 2
    zero_ks_kernel<<<4, 1024>>>(4096);                 // launch 3
    proj_kernel<<<dim3(16, 64), 256>>>(x, W, bias);    // launch 4 (profiled)
    attn_kernel<<<2048, 256, SMEM2>>>();               // launch 5
    build_kernel<<<1024, 256>>>();                     // launch 6
    colsum_kernel<<<512, 256>>>();                     // launch 7
    topk_kernel<<<8, 256>>>(x);                        // launch 8
    add_kernel<<<(BB * CC * NN) / 1024, 256>>>(x, out);// launch 9
}

// round 17
// speedup vs baseline: 1.0866x; 1.0129x over previous
#include <cuda_runtime.h>
#include <cuda_fp16.h>
#include <math_constants.h>

#define BB 8
#define CC 512
#define NN 1024
#define HH 8
#define DD 64

// Q/K stored d-major per (b,h):  g_q[((b*HH+h)*DD + d)*NN + n]
__device__ float  g_q[BB*HH*NN*DD];
__device__ float  g_k[BB*HH*NN*DD];
__device__ __half g_s[(size_t)BB*HH*NN*NN];  // 128 MB: unscaled exp'd scores
__device__ float  g_rsinv[BB*HH*NN];         // fp32 1/rowsum per (b,h,q)
__device__ float  g_attn[BB*NN*NN];          // head-summed attn
__device__ double g_rinv[BB*NN];             // 1 / row-sum of exp(attn/256)
__device__ double g_ksc[BB*NN];              // key_scores accumulators (fp64)
__device__ float  g_mp[BB*CC];               // max-pooled (B, C)

// ---- packed f32x2 helpers ---------------------------------------------------
__device__ __forceinline__ unsigned long long f2pack(float lo, float hi) {
    unsigned long long r;
    asm("mov.b64 %0, {%1, %2};" : "=l"(r) : "f"(lo), "f"(hi));
    return r;
}
__device__ __forceinline__ unsigned long long ffma2(unsigned long long a,
                                                    unsigned long long b,
                                                    unsigned long long c) {
    unsigned long long d;
    asm("fma.rn.f32x2 %0, %1, %2, %3;" : "=l"(d) : "l"(a), "l"(b), "l"(c));
    return d;
}
__device__ __forceinline__ float2 f2unpack(unsigned long long v) {
    float lo, hi;
    asm("mov.b64 {%0, %1}, %2;" : "=f"(lo), "=f"(hi) : "l"(v));
    return make_float2(lo, hi);
}
__device__ __forceinline__ float ex2f(float x) {
    float y;
    asm("ex2.approx.ftz.f32 %0, %1;" : "=f"(y) : "f"(x));
    return y;
}
// pack two fp32 into f16x2: lo half = first arg
__device__ __forceinline__ unsigned int h2pack(float lo, float hi) {
    unsigned int d;
    asm("cvt.rn.f16x2.f32 %0, %1, %2;" : "=r"(d) : "f"(hi), "f"(lo));
    return d;
}
// async copies global->shared
__device__ __forceinline__ void cp_async4(unsigned int saddr, const float* g) {
    asm volatile("cp.async.ca.shared.global [%0], [%1], 4;" :: "r"(saddr), "l"(g));
}
__device__ __forceinline__ void cp_async16(unsigned int saddr, const float* g) {
    asm volatile("cp.async.cg.shared.global [%0], [%1], 16;" :: "r"(saddr), "l"(g));
}

// exp(x) for x in [0, 1/32], fp32 degree-4 Taylor (round-6 error budget).
__device__ __forceinline__ float exp_small_f(float x) {
    float p = 1.f / 24.f;
    p = fmaf(p, x, 1.f / 6.f);
    p = fmaf(p, x, 0.5f);
    p = fmaf(p, x, 1.f);
    p = fmaf(p, x, 1.f);
    return p;
}

// ---------------------------------------------------------------------------
// Kernel 1: fused Q/K projection. Tile 128m x 64j, microtile 8m x 4j.
// cp.async double-buffered; As staged with 16B copies (2 ops/thread/tile).
// ---------------------------------------------------------------------------
#define AS_STRIDE 132
#define AS_BUF    (16 * AS_STRIDE)   // 2112 floats
#define BS_STRIDE 68
#define BS_BUF    (16 * BS_STRIDE)   // 1088 floats

__global__ __launch_bounds__(256) void proj_kernel(const float* __restrict__ x,
                                                   const float* __restrict__ W,
                                                   const float* __restrict__ bias) {
    __shared__ float As[2 * AS_BUF];
    __shared__ float Bs[2 * BS_BUF];
    int tid = threadIdx.x;
    int tx  = tid & 31;
    int wid = tid >> 5;
    int jq  = tx & 15;
    int mg  = wid * 2 + (tx >> 4);
    int j0 = blockIdx.x * 64;
    int m0 = blockIdx.y * 128;
    int b  = m0 >> 10;
    int n0 = m0 & 1023;
    const float* xb = x + (size_t)b * CC * NN;

    unsigned int as_base = (unsigned int)__cvta_generic_to_shared(As);
    unsigned int bs_base = (unsigned int)__cvta_generic_to_shared(Bs);

    // As staging (float4 granularity): 512 float4 per tile, 2 per thread
    int akk0 = tid >> 5;            // row for first copy (idx = tid)
    int am0  = (tid & 31) * 4;
    int akk1 = (tid + 256) >> 5;    // row for second copy
    int am1  = am0;                 // same (idx&31)
    // Bs staging (scalar): 4 per thread
    int bkk = tid & 15;
    int bjl = tid >> 4;

    unsigned long long acc[4][4];
    #pragma unroll
    for (int i = 0; i < 4; i++)
        #pragma unroll
        for (int j = 0; j < 4; j++) acc[i][j] = 0ull;

    // issue k-tile 0 into buffer 0
    cp_async16(as_base + (unsigned)(akk0 * AS_STRIDE + am0) * 4,
               &xb[akk0 * NN + n0 + am0]);
    cp_async16(as_base + (unsigned)(akk1 * AS_STRIDE + am1) * 4,
               &xb[akk1 * NN + n0 + am1]);
    #pragma unroll
    for (int p = 0; p < 4; p++) {
        int jl = bjl + p * 16;
        cp_async4(bs_base + (unsigned)(bkk * BS_STRIDE + jl) * 4,
                  &W[(size_t)(j0 + jl) * CC + bkk]);
    }
    asm volatile("cp.async.commit_group;");

    for (int i = 0; i < 32; i++) {
        int buf = i & 1;
        if (i < 31) {
            int kb = (i + 1) * 16;
            int nbuf = 1 - buf;
            cp_async16(as_base + (unsigned)(nbuf * AS_BUF + akk0 * AS_STRIDE + am0) * 4,
                       &xb[(kb + akk0) * NN + n0 + am0]);
            cp_async16(as_base + (unsigned)(nbuf * AS_BUF + akk1 * AS_STRIDE + am1) * 4,
                       &xb[(kb + akk1) * NN + n0 + am1]);
            #pragma unroll
            for (int p = 0; p < 4; p++) {
                int jl = bjl + p * 16;
                cp_async4(bs_base + (unsigned)(nbuf * BS_BUF + bkk * BS_STRIDE + jl) * 4,
                          &W[(size_t)(j0 + jl) * CC + kb + bkk]);
            }
            asm volatile("cp.async.commit_group;");
            asm volatile("cp.async.wait_group 1;");
        } else {
            asm volatile("cp.async.wait_group 0;");
        }
        __syncthreads();

        const float* Asb = As + buf * AS_BUF;
        const float* Bsb = Bs + buf * BS_BUF;
        #pragma unroll
        for (int kk = 0; kk < 16; kk++) {
            float4 a0 = *(const float4*)&Asb[kk * AS_STRIDE + mg * 8];
            float4 a1 = *(const float4*)&Asb[kk * AS_STRIDE + mg * 8 + 4];
            float4 bq = *(const float4*)&Bsb[kk * BS_STRIDE + 4 * jq];
            unsigned long long A[4] = { f2pack(a0.x, a0.y), f2pack(a0.z, a0.w),
                                        f2pack(a1.x, a1.y), f2pack(a1.z, a1.w) };
            unsigned long long Bd[4] = { f2pack(bq.x, bq.x), f2pack(bq.y, bq.y),
                                         f2pack(bq.z, bq.z), f2pack(bq.w, bq.w) };
            #pragma unroll
            for (int am = 0; am < 4; am++)
                #pragma unroll
                for (int j = 0; j < 4; j++)
                    acc[am][j] = ffma2(A[am], Bd[j], acc[am][j]);
        }
        __syncthreads();
    }

    #pragma unroll
    for (int j = 0; j < 4; j++) {
        int jg = j0 + 4 * jq + j;
        float bsv = bias[jg];
        int head = (jg & 511) >> 6;
        int dd   = jg & 63;
        float* dst = ((jg < 512) ? g_q : g_k)
                   + ((size_t)(b * HH + head) * DD + dd) * NN + n0 + mg * 8;
        float2 u0 = f2unpack(acc[0][j]);
        float2 u1 = f2unpack(acc[1][j]);
        float2 u2 = f2unpack(acc[2][j]);
        float2 u3 = f2unpack(acc[3][j]);
        *(float4*)&dst[0] = make_float4(u0.x + bsv, u0.y + bsv, u1.x + bsv, u1.y + bsv);
        *(float4*)&dst[4] = make_float4(u2.x + bsv, u2.y + bsv, u3.x + bsv, u3.y + bsv);
    }
}

// ---------------------------------------------------------------------------
// Kernel 2: per-(b,h,32q) exp'd scores -> g_s (fp16, unscaled) + 1/rowsum.
// (R13 version, known good: 3 blocks/SM, 8q x 4k microtile.)
// ---------------------------------------------------------------------------
#define QS_STRIDE 36
#define KS_STRIDE 260
#define SM_QS   0
#define SM_KS   (64*QS_STRIDE)
#define SM_RP   (SM_KS + 64*KS_STRIDE)
#define SMEM2   ((SM_RP + 64) * 4)

__global__ __launch_bounds__(256, 3) void attn_kernel() {
    extern __shared__ float sm[];
    float* Qs    = sm + SM_QS;     // [64 d][36: 32q + pad]
    float* Ks    = sm + SM_KS;     // [64 d][260: 256k + pad]
    float* rpart = sm + SM_RP;     // [2 strips][32 rows]

    const float QSCALE = 0.18033688f;          // log2(e)/8
    int tid = threadIdx.x;
    int b  = blockIdx.x >> 8;
    int h  = (blockIdx.x >> 5) & 7;
    int q0 = (blockIdx.x & 31) << 5;
    int tx = tid & 31, w = tid >> 5;
    int qg = (w & 3) * 8;
    int ks = w >> 2;
    int kbase = ks * 128 + 4 * tx;
    const unsigned long long NEG4 = f2pack(-4.f, -4.f);

    const float* Qg = g_q + (size_t)(b * HH + h) * DD * NN + q0;
    const float* Kg = g_k + (size_t)(b * HH + h) * DD * NN;
    __half* Sg = g_s + ((size_t)((b * HH + h) * NN) + q0) * NN;

    #pragma unroll
    for (int it = 0; it < 2; it++) {           // Qs: 64d x 32q, prescaled
        int e = tid + it * 256;
        int dd = e >> 3, q4 = (e & 7) * 4;
        float4 v = *(const float4*)&Qg[(size_t)dd * NN + q4];
        *(float4*)&Qs[dd * QS_STRIDE + q4] =
            make_float4(v.x * QSCALE, v.y * QSCALE, v.z * QSCALE, v.w * QSCALE);
    }

    float rowpart[8] = {0.f,0.f,0.f,0.f,0.f,0.f,0.f,0.f};

    for (int kt = 0; kt < 4; kt++) {
        int k0 = kt * 256;
        __syncthreads();
        #pragma unroll
        for (int it = 0; it < 16; it++) {      // Ks: 64d x 256k
            int e = tid + it * 256;
            int dd = e >> 6, r4 = (e & 63) * 4;
            float4 v = *(const float4*)&Kg[(size_t)dd * NN + k0 + r4];
            *(float4*)&Ks[dd * KS_STRIDE + r4] = v;
        }
        __syncthreads();

        unsigned long long acc[4][4];
        #pragma unroll
        for (int i = 0; i < 4; i++)
            #pragma unroll
            for (int j = 0; j < 4; j++) acc[i][j] = NEG4;

        #pragma unroll 8
        for (int kk = 0; kk < 64; kk++) {
            float4 a0 = *(const float4*)&Qs[kk * QS_STRIDE + qg];
            float4 a1 = *(const float4*)&Qs[kk * QS_STRIDE + qg + 4];
            float4 bv = *(const float4*)&Ks[kk * KS_STRIDE + kbase];
            unsigned long long A[4] = { f2pack(a0.x, a0.y), f2pack(a0.z, a0.w),
                                        f2pack(a1.x, a1.y), f2pack(a1.z, a1.w) };
            unsigned long long Bd[4] = { f2pack(bv.x, bv.x), f2pack(bv.y, bv.y),
                                         f2pack(bv.z, bv.z), f2pack(bv.w, bv.w) };
            #pragma unroll
            for (int qq = 0; qq < 4; qq++)
                #pragma unroll
                for (int kc = 0; kc < 4; kc++)
                    acc[qq][kc] = ffma2(A[qq], Bd[kc], acc[qq][kc]);
        }

        // e' = 2^(y-4); rowparts; STG 4 halves per row (unscaled)
        #pragma unroll
        for (int qq = 0; qq < 4; qq++) {
            float elo[4], ehi[4];
            float slo = 0.f, shi = 0.f;
            #pragma unroll
            for (int kc = 0; kc < 4; kc++) {
                float2 u = f2unpack(acc[qq][kc]);
                elo[kc] = ex2f(u.x); ehi[kc] = ex2f(u.y);
                slo += elo[kc]; shi += ehi[kc];
            }
            rowpart[2*qq]   += slo;
            rowpart[2*qq+1] += shi;
            uint2 plo = make_uint2(h2pack(elo[0], elo[1]), h2pack(elo[2], elo[3]));
            uint2 phi = make_uint2(h2pack(ehi[0], ehi[1]), h2pack(ehi[2], ehi[3]));
            *(uint2*)&Sg[(size_t)(qg + 2*qq)     * NN + k0 + kbase] = plo;
            *(uint2*)&Sg[(size_t)(qg + 2*qq + 1) * NN + k0 + kbase] = phi;
        }
    }

    #pragma unroll
    for (int i = 0; i < 8; i++) {
        float s = rowpart[i];
        #pragma unroll
        for (int o = 16; o; o >>= 1) s += __shfl_xor_sync(~0u, s, o);
        if (tx == 0) rpart[ks * 32 + qg + i] = s;
    }
    __syncthreads();
    if (tid < 32)
        g_rsinv[(b * HH + h) * NN + q0 + tid] = 1.f / (rpart[tid] + rpart[32 + tid]);
}

// ---------------------------------------------------------------------------
// Kernel 3: build attn = sum_h e_h * rinv_h (R13 version, known good),
// write g_attn + fp64 w2 rowsum -> g_rinv. Warp per q-row, barrier-free.
// ---------------------------------------------------------------------------
__global__ __launch_bounds__(256) void build_kernel() {
    int row  = blockIdx.x * 8 + (threadIdx.x >> 5);   // b*1024 + q
    int lane = threadIdx.x & 31;
    int b = row >> 10;
    int q = row & 1023;

    const __half* sp = g_s + ((size_t)(b * HH) * NN + q) * NN;
    float rinv8[8];
    #pragma unroll
    for (int h = 0; h < 8; h++) rinv8[h] = g_rsinv[(b * HH + h) * NN + q];

    float* gp = g_attn + (size_t)row * NN;
    double w0 = 0.0, w1 = 0.0;
    #pragma unroll 2
    for (int c = 0; c < 16; c++) {
        int k = c * 64 + lane * 2;
        float a0 = 0.f, a1 = 0.f;
        #pragma unroll
        for (int h = 0; h < 8; h++) {
            __half2 hv = *(const __half2*)(sp + (size_t)h * NN * NN + k);
            float2 f = __half22float2(hv);
            a0 = fmaf(f.x, rinv8[h], a0);
            a1 = fmaf(f.y, rinv8[h], a1);
        }
        *(float2*)&gp[k] = make_float2(a0, a1);
        w0 += (double)exp_small_f(a0 * (1.f / 256.f));
        w1 += (double)exp_small_f(a1 * (1.f / 256.f));
    }
    double ws = w0 + w1;
    #pragma unroll
    for (int o = 16; o; o >>= 1) ws += __shfl_xor_sync(~0u, ws, o);
    if (lane == 0) g_rinv[row] = 1.0 / ws;
}

// ---------------------------------------------------------------------------
// Kernel 4: column accumulation (R6 version). 16-row chunks, 4 cols/thread.
// ---------------------------------------------------------------------------
__global__ void zero_ks_kernel(int off) {
    g_ksc[off + blockIdx.x * 1024 + threadIdx.x] = 0.0;
}

__global__ __launch_bounds__(256) void colsum_kernel() {
    int b  = blockIdx.x >> 6;
    int q0 = (blockIdx.x & 63) << 4;
    int tid = threadIdx.x;
    const float* base = g_attn + ((size_t)b * NN + q0) * NN;
    const double* rinv = g_rinv + b * NN + q0;

    double acc[4] = {0.0, 0.0, 0.0, 0.0};
    #pragma unroll 4
    for (int q = 0; q < 16; q++) {
        const float* row = base + (size_t)q * NN;
        double inv = rinv[q];
        float e[4];
        #pragma unroll
        for (int j = 0; j < 4; j++) e[j] = exp_small_f(row[tid + j * 256] * (1.f / 256.f));
        #pragma unroll
        for (int j = 0; j < 4; j++) acc[j] = fma((double)e[j], inv, acc[j]);
    }
    #pragma unroll
    for (int j = 0; j < 4; j++)
        atomicAdd(&g_ksc[b * NN + tid + j * 256], acc[j] * (1.0 / 1024.0));
}

// ---------------------------------------------------------------------------
// Kernel 5: top-8 per batch, fp32-quantized compares + lowest-index ties.
// ---------------------------------------------------------------------------
__global__ __launch_bounds__(256) void topk_kernel(const float* __restrict__ x) {
    __shared__ float bvv[8];
    __shared__ int   bii[8];
    __shared__ int   sel[8];
    __shared__ int   sbi;
    int b = blockIdx.x;
    int tid = threadIdx.x;
    int lane = tid & 31, warp = tid >> 5;

    float v[4]; int idx[4];
    #pragma unroll
    for (int j = 0; j < 4; j++) {
        idx[j] = tid + j * 256;
        v[j] = (float)g_ksc[b * NN + idx[j]];
    }

    for (int it = 0; it < 8; it++) {
        float mv = v[0]; int mi = idx[0];
        #pragma unroll
        for (int j = 1; j < 4; j++)
            if (v[j] > mv || (v[j] == mv && idx[j] < mi)) { mv = v[j]; mi = idx[j]; }
        #pragma unroll
        for (int o = 16; o; o >>= 1) {
            float ov = __shfl_xor_sync(~0u, mv, o);
            int   oi = __shfl_xor_sync(~0u, mi, o);
            if (ov > mv || (ov == mv && oi < mi)) { mv = ov; mi = oi; }
        }
        if (lane == 0) { bvv[warp] = mv; bii[warp] = mi; }
        __syncthreads();
        if (tid == 0) {
            float m2 = bvv[0]; int i2 = bii[0];
            for (int ww = 1; ww < 8; ww++)
                if (bvv[ww] > m2 || (bvv[ww] == m2 && bii[ww] < i2)) { m2 = bvv[ww]; i2 = bii[ww]; }
            sel[it] = i2; sbi = i2;
        }
        __syncthreads();
        int si = sbi;
        #pragma unroll
        for (int j = 0; j < 4; j++) if (idx[j] == si) v[j] = -CUDART_INF_F;
        __syncthreads();
    }

    for (int c = tid; c < CC; c += 256) {
        const float* xb = x + ((size_t)(b * CC + c)) * NN;
        float m = -CUDART_INF_F;
        #pragma unroll
        for (int j = 0; j < 8; j++) m = fmaxf(m, xb[sel[j]]);
        g_mp[b * CC + c] = m;
    }
}

// ---------------------------------------------------------------------------
// Kernel 6: out = x + max_pooled broadcast (float4)
// ---------------------------------------------------------------------------
__global__ void add_kernel(const float* __restrict__ x, float* __restrict__ out) {
    int i = blockIdx.x * 256 + threadIdx.x;
    int bc = i >> 8;
    float4 xv = ((const float4*)x)[i];
    float m = g_mp[bc];
    ((float4*)out)[i] = make_float4(xv.x + m, xv.y + m, xv.z + m, xv.w + m);
}

// ---------------------------------------------------------------------------
extern "C" void kernel_launch(void* const* d_in, const int* in_sizes, int n_in,
                              void* d_out, int out_size) {
    const float* x    = (const float*)d_in[0];
    const float* W    = (const float*)d_in[1];
    const float* bias = (const float*)d_in[2];
    float* out = (float*)d_out;

    cudaFuncSetAttribute(attn_kernel, cudaFuncAttributeMaxDynamicSharedMemorySize, SMEM2);

    zero_ks_kernel<<<2, 1024>>>(0);                    // launch 1
    zero_ks_kernel<<<2, 1024>>>(2048);                 // launch 2
    zero_ks_kernel<<<4, 1024>>>(4096);                 // launch 3
    proj_kernel<<<dim3(16, 64), 256>>>(x, W, bias);    // launch 4 (profiled)
    attn_kernel<<<2048, 256, SMEM2>>>();               // launch 5
    build_kernel<<<1024, 256>>>();                     // launch 6
    colsum_kernel<<<512, 256>>>();                     // launch 7
    topk_kernel<<<8, 256>>>(x);                        // launch 8
    add_kernel<<<(BB * CC * NN) / 1024, 256>>>(x, out);// launch 9
}